// round 3
// baseline (speedup 1.0000x reference)
#include <cuda_runtime.h>

// Problem constants
#define BB 4
#define CC 12
#define HH0 512
#define HH1 256
#define NBC (BB*CC)          // 48
#define NSCALES 5
#define TS 32                // output tile side
#define TIN 42               // input tile span (TS + 10)
#define SPITCH 43            // sx/sy row pitch (bank-conflict-free for stage1 reads)
#define HPITCH 33            // hb row pitch (conflict-free stage1 writes + stage2 reads)
#define NTHR 192

// Gaussian weights, win=11 sigma=1.5, normalized (compile-time constants -> FFMA-imm).
#define GW0 0.00102838f
#define GW1 0.00759870f
#define GW2 0.03600080f
#define GW3 0.10936070f
#define GW4 0.21300560f
#define GW5 0.26601180f
__device__ __constant__ const float c_dummy = 0.f; // keep TU non-empty constants

__device__ float g_x0[(size_t)NBC*HH0*HH0];
__device__ float g_y0[(size_t)NBC*HH0*HH0];
__device__ float g_x1[(size_t)NBC*HH1*HH1];
__device__ float g_y1[(size_t)NBC*HH1*HH1];
__device__ float g_ss[NSCALES*NBC];
__device__ float g_cs[NSCALES*NBC];

__device__ __forceinline__ float* slot_x(int s) { return s ? g_x1 : g_x0; }
__device__ __forceinline__ float* slot_y(int s) { return s ? g_y1 : g_y0; }

// ---------------------------------------------------------------------------
__global__ void zero_acc() {
    int t = threadIdx.x;
    if (t < NSCALES*NBC) { g_ss[t] = 0.f; g_cs[t] = 0.f; }
}

// ---------------------------------------------------------------------------
__global__ __launch_bounds__(256) void softmax_onehot(
    const float* __restrict__ pred, const int* __restrict__ tgt)
{
    const int HW = HH0*HH0;
    int p = blockIdx.x*blockDim.x + threadIdx.x;
    if (p >= BB*HW) return;
    int b  = p / HW;
    int hw = p - b*HW;
    const float* pp = pred + (size_t)b*CC*HW + hw;

    float v[CC];
    float mx = -1e30f;
#pragma unroll
    for (int c = 0; c < CC; c++) { v[c] = pp[(size_t)c*HW]; mx = fmaxf(mx, v[c]); }
    float s = 0.f;
#pragma unroll
    for (int c = 0; c < CC; c++) { v[c] = expf(v[c]-mx); s += v[c]; }
    float inv = 1.f/s;
    int t = tgt[p];
    size_t base = (size_t)b*CC*HW + hw;
#pragma unroll
    for (int c = 0; c < CC; c++) {
        g_x0[base + (size_t)c*HW] = v[c]*inv;
        g_y0[base + (size_t)c*HW] = (c == t) ? 1.f : 0.f;
    }
}

// ---------------------------------------------------------------------------
// Fused 2x2 average pool for both x (blockIdx.y==0) and y (blockIdx.y==1).
// float2 vectorized loads.
__global__ __launch_bounds__(256) void pool2(int src, int dst, int Hs)
{
    int Hd = Hs >> 1;
    int N  = NBC * Hd * Hd;
    int i = blockIdx.x*blockDim.x + threadIdx.x;
    if (i >= N) return;
    int which = blockIdx.y;
    int w  = i % Hd;
    int h  = (i / Hd) % Hd;
    int bc = i / (Hd*Hd);
    const float* S = which ? slot_y(src) : slot_x(src);
    float*       D = which ? slot_y(dst) : slot_x(dst);
    const float2* r0 = (const float2*)(S + (size_t)bc*Hs*Hs + (size_t)(2*h)*Hs);
    const float2* r1 = (const float2*)(S + (size_t)bc*Hs*Hs + (size_t)(2*h+1)*Hs);
    float2 a = r0[w], b = r1[w];
    D[(size_t)bc*Hd*Hd + (size_t)h*Hd + w] = (a.x + a.y + b.x + b.y)*0.25f;
}

// ---------------------------------------------------------------------------
// Separable SSIM with register sliding windows.
// Stage1 (168 threads): horizontal blur, each thread does 8 consecutive cols.
// Stage2 (128 threads): vertical blur + SSIM map, each thread does 8 rows.
__global__ __launch_bounds__(NTHR) void ssim_kernel(int slot, int Hs, int sidx)
{
    const int OH = Hs - 10;
    __shared__ float sx[TIN][SPITCH];
    __shared__ float sy[TIN][SPITCH];
    __shared__ float hb0[TIN][HPITCH];
    __shared__ float hb1[TIN][HPITCH];
    __shared__ float hb2[TIN][HPITCH];
    __shared__ float hb3[TIN][HPITCH];
    __shared__ float hb4[TIN][HPITCH];
    __shared__ float rss[NTHR/32], rcs[NTHR/32];

    int bc  = blockIdx.z;
    int ty0 = blockIdx.y*TS, tx0 = blockIdx.x*TS;
    const float* xp = slot_x(slot) + (size_t)bc*Hs*Hs;
    const float* yp = slot_y(slot) + (size_t)bc*Hs*Hs;
    int tid = threadIdx.x;

    // Load (TIN x TIN) x/y tile; zero-fill outside (outputs masked later).
    for (int i = tid; i < TIN*TIN; i += NTHR) {
        int r = i / TIN, c = i - r*TIN;
        int ih = ty0 + r, iw = tx0 + c;
        float xv = 0.f, yv = 0.f;
        if (ih < Hs && iw < Hs) {
            size_t o = (size_t)ih*Hs + iw;
            xv = xp[o]; yv = yp[o];
        }
        sx[r][c] = xv; sy[r][c] = yv;
    }
    __syncthreads();

    // Stage 1: horizontal blur of 5 fields, 8-col strips.
    if (tid < TIN*4) {
        int r  = tid >> 2;
        int c0 = (tid & 3) << 3;
        float xw[18], yw[18];
#pragma unroll
        for (int i = 0; i < 18; i++) { xw[i] = sx[r][c0+i]; yw[i] = sy[r][c0+i]; }
        float xxw[18], yyw[18], xyw[18];
#pragma unroll
        for (int i = 0; i < 18; i++) {
            xxw[i] = xw[i]*xw[i]; yyw[i] = yw[i]*yw[i]; xyw[i] = xw[i]*yw[i];
        }
#pragma unroll
        for (int j = 0; j < 8; j++) {
            float hx=0.f, hy=0.f, hxx=0.f, hyy=0.f, hxy=0.f;
#pragma unroll
            for (int k = 0; k < 11; k++) {
                const float g = (k==0||k==10) ? GW0 : (k==1||k==9) ? GW1 :
                                (k==2||k==8)  ? GW2 : (k==3||k==7) ? GW3 :
                                (k==4||k==6)  ? GW4 : GW5;
                hx  = fmaf(g, xw[j+k],  hx);
                hy  = fmaf(g, yw[j+k],  hy);
                hxx = fmaf(g, xxw[j+k], hxx);
                hyy = fmaf(g, yyw[j+k], hyy);
                hxy = fmaf(g, xyw[j+k], hxy);
            }
            hb0[r][c0+j]=hx; hb1[r][c0+j]=hy; hb2[r][c0+j]=hxx;
            hb3[r][c0+j]=hyy; hb4[r][c0+j]=hxy;
        }
    }
    __syncthreads();

    // Stage 2: vertical blur + SSIM, 8-row strips per column.
    float lss = 0.f, lcs = 0.f;
    if (tid < 128) {
        int c  = tid & 31;
        int r0 = (tid >> 5) << 3;
        float w0[18], w1[18], w2[18], w3[18], w4[18];
#pragma unroll
        for (int i = 0; i < 18; i++) {
            w0[i]=hb0[r0+i][c]; w1[i]=hb1[r0+i][c]; w2[i]=hb2[r0+i][c];
            w3[i]=hb3[r0+i][c]; w4[i]=hb4[r0+i][c];
        }
        int ow = tx0 + c;
#pragma unroll
        for (int j = 0; j < 8; j++) {
            float m1=0.f, m2=0.f, e11=0.f, e22=0.f, e12=0.f;
#pragma unroll
            for (int k = 0; k < 11; k++) {
                const float g = (k==0||k==10) ? GW0 : (k==1||k==9) ? GW1 :
                                (k==2||k==8)  ? GW2 : (k==3||k==7) ? GW3 :
                                (k==4||k==6)  ? GW4 : GW5;
                m1  = fmaf(g, w0[j+k], m1);
                m2  = fmaf(g, w1[j+k], m2);
                e11 = fmaf(g, w2[j+k], e11);
                e22 = fmaf(g, w3[j+k], e22);
                e12 = fmaf(g, w4[j+k], e12);
            }
            int oh = ty0 + r0 + j;
            if (oh < OH && ow < OH) {
                float m11 = m1*m1, m22 = m2*m2, m12 = m1*m2;
                float v1  = e11 - m11, v2 = e22 - m22, cov = e12 - m12;
                float cs  = __fdividef(2.f*cov + 0.0009f, v1 + v2 + 0.0009f);
                float ss  = __fdividef(2.f*m12 + 0.0001f, m11 + m22 + 0.0001f) * cs;
                lss += ss; lcs += cs;
            }
        }
    }

    // Block reduction -> atomicAdd into per-(scale, bc) accumulators.
#pragma unroll
    for (int o = 16; o; o >>= 1) {
        lss += __shfl_down_sync(0xffffffffu, lss, o);
        lcs += __shfl_down_sync(0xffffffffu, lcs, o);
    }
    if ((tid & 31) == 0) { rss[tid>>5] = lss; rcs[tid>>5] = lcs; }
    __syncthreads();
    if (tid == 0) {
        float ts = 0.f, tc = 0.f;
#pragma unroll
        for (int w = 0; w < NTHR/32; w++) { ts += rss[w]; tc += rcs[w]; }
        atomicAdd(&g_ss[sidx*NBC + bc], ts);
        atomicAdd(&g_cs[sidx*NBC + bc], tc);
    }
}

// ---------------------------------------------------------------------------
__global__ void finalize(float* __restrict__ out)
{
    __shared__ float sm[NBC];
    int t = threadIdx.x;
    const float Wt[5]  = {0.0448f, 0.2856f, 0.3001f, 0.2363f, 0.1333f};
    const float cnt[5] = {502.f*502.f, 246.f*246.f, 118.f*118.f, 54.f*54.f, 22.f*22.f};
    if (t < NBC) {
        float ms = 1.f;
#pragma unroll
        for (int s = 0; s < NSCALES; s++) {
            float acc = (s == NSCALES-1) ? g_ss[s*NBC + t] : g_cs[s*NBC + t];
            float v = fmaxf(acc / cnt[s], 0.f);
            ms *= powf(v, Wt[s]);
        }
        sm[t] = ms;
    }
    __syncthreads();
    if (t == 0) {
        float a = 0.f;
#pragma unroll
        for (int i = 0; i < NBC; i++) a += sm[i];
        out[0] = 1.f - a / (float)NBC;
    }
}

// ---------------------------------------------------------------------------
extern "C" void kernel_launch(void* const* d_in, const int* in_sizes, int n_in,
                              void* d_out, int out_size)
{
    const float* pred = (const float*)d_in[0];
    const int*   tgt  = (const int*)d_in[1];
    float*       out  = (float*)d_out;

    zero_acc<<<1, 256>>>();

    int np = BB*HH0*HH0;
    softmax_onehot<<<(np + 255)/256, 256>>>(pred, tgt);

    int Hs = HH0;
    for (int s = 0; s < NSCALES; s++) {
        if (s > 0) {
            int src = (s-1) & 1, dst = s & 1;
            int Hd = Hs >> 1;
            int N  = NBC*Hd*Hd;
            dim3 pg((N + 255)/256, 2);
            pool2<<<pg, 256>>>(src, dst, Hs);
            Hs = Hd;
        }
        int slot = s & 1;
        int OH = Hs - 10;
        int nt = (OH + TS - 1)/TS;
        dim3 grid(nt, nt, NBC);
        ssim_kernel<<<grid, NTHR>>>(slot, Hs, s);
    }

    finalize<<<1, 64>>>(out);
}

// round 4
// speedup vs baseline: 1.7537x; 1.7537x over previous
#include <cuda_runtime.h>

#define BB 4
#define CC 12
#define HH0 512
#define NBC (BB*CC)          // 48
#define NSCALES 5
#define TS 32
#define TIN 42               // TS + 10
#define SPITCH 43
#define HPITCH 33
#define NTHR 192

__device__ float g_x0[(size_t)NBC*HH0*HH0];
__device__ float g_px1[(size_t)NBC*256*256];
__device__ float g_py1[(size_t)NBC*256*256];
__device__ float g_px2[(size_t)NBC*128*128];
__device__ float g_py2[(size_t)NBC*128*128];
__device__ float g_px3[(size_t)NBC*64*64];
__device__ float g_py3[(size_t)NBC*64*64];
__device__ float g_px4[(size_t)NBC*32*32];
__device__ float g_py4[(size_t)NBC*32*32];
__device__ float g_ss[NSCALES*NBC];
__device__ float g_cs[NSCALES*NBC];

__device__ __forceinline__ float* in_x(int s) {
    switch (s) { case 0: return g_x0; case 1: return g_px1; case 2: return g_px2;
                 case 3: return g_px3; default: return g_px4; }
}
__device__ __forceinline__ float* in_y(int s) {
    switch (s) { case 1: return g_py1; case 2: return g_py2;
                 case 3: return g_py3; default: return g_py4; }
}

// ---------------------------------------------------------------------------
// Softmax over C -> g_x0. Block 0 also zeros the accumulators.
__global__ __launch_bounds__(256) void softmax_x0(
    const float* __restrict__ pred, const int* __restrict__ tgt)
{
    if (blockIdx.x == 0 && threadIdx.x < NSCALES*NBC) {
        g_ss[threadIdx.x] = 0.f; g_cs[threadIdx.x] = 0.f;
    }
    const int HW = HH0*HH0;
    int p = blockIdx.x*blockDim.x + threadIdx.x;
    if (p >= BB*HW) return;
    int b  = p / HW;
    int hw = p - b*HW;
    const float* pp = pred + (size_t)b*CC*HW + hw;

    float v[CC];
    float mx = -1e30f;
#pragma unroll
    for (int c = 0; c < CC; c++) { v[c] = pp[(size_t)c*HW]; mx = fmaxf(mx, v[c]); }
    float s = 0.f;
#pragma unroll
    for (int c = 0; c < CC; c++) { v[c] = expf(v[c]-mx); s += v[c]; }
    float inv = 1.f/s;
    size_t base = (size_t)b*CC*HW + hw;
#pragma unroll
    for (int c = 0; c < CC; c++) g_x0[base + (size_t)c*HW] = v[c]*inv;
}

// ---------------------------------------------------------------------------
// Separable SSIM + fused 2x2 pooling for the next scale.
// S0: y is derived from tgt (one-hot), and conv(y^2) == conv(y).
template<bool S0>
__global__ __launch_bounds__(NTHR) void ssim_kernel(
    const int* __restrict__ tgt, int Hs, int sidx)
{
    const int OH = Hs - 10;
    __shared__ float sx[TIN][SPITCH];
    __shared__ float sy[TIN][SPITCH];
    __shared__ float hb0[TIN][HPITCH];
    __shared__ float hb1[TIN][HPITCH];
    __shared__ float hb2[TIN][HPITCH];
    __shared__ float hb3[TIN][HPITCH];
    __shared__ float hb4[TIN][HPITCH];
    __shared__ float rss[NTHR/32], rcs[NTHR/32];

    int bc  = blockIdx.z;
    int tid = threadIdx.x;
    int ty0 = blockIdx.y*TS, tx0 = blockIdx.x*TS;
    const float* xp = in_x(sidx) + (size_t)bc*Hs*Hs;
    const float* yp = S0 ? nullptr : (in_y(sidx) + (size_t)bc*Hs*Hs);
    const int*   tp = S0 ? (tgt + (size_t)(bc/CC)*Hs*Hs) : nullptr;
    int cls = bc % CC;

    // Load tile (zero-fill beyond image; those outputs masked).
    for (int i = tid; i < TIN*TIN; i += NTHR) {
        int r = i / TIN, c = i - r*TIN;
        int ih = ty0 + r, iw = tx0 + c;
        float xv = 0.f, yv = 0.f;
        if (ih < Hs && iw < Hs) {
            int o = ih*Hs + iw;
            xv = xp[o];
            yv = S0 ? ((tp[o] == cls) ? 1.f : 0.f) : yp[o];
        }
        sx[r][c] = xv; sy[r][c] = yv;
    }
    __syncthreads();

    // Fused 2x2 pooling of this tile's own 32x32 region -> next-scale input.
    if (sidx < 4) {
        int Hd = Hs >> 1;
        float* xo = in_x(sidx+1) + (size_t)bc*Hd*Hd;
        float* yo = in_y(sidx+1) + (size_t)bc*Hd*Hd;
        int ph0 = blockIdx.y*16, pw0 = blockIdx.x*16;
        for (int i = tid; i < 256; i += NTHR) {
            int pr = i >> 4, pc = i & 15;
            int r = pr*2, c = pc*2;
            float px = (sx[r][c]+sx[r][c+1]+sx[r+1][c]+sx[r+1][c+1])*0.25f;
            float py = (sy[r][c]+sy[r][c+1]+sy[r+1][c]+sy[r+1][c+1])*0.25f;
            int po = (ph0+pr)*Hd + (pw0+pc);
            xo[po] = px; yo[po] = py;
        }
    }

    constexpr float G[11] = {0.00102838f,0.00759870f,0.03600080f,0.10936070f,
                             0.21300560f,0.26601180f,0.21300560f,0.10936070f,
                             0.03600080f,0.00759870f,0.00102838f};

    // Stage 1: horizontal blur, 8-col strips, scatter accumulation.
    if (tid < TIN*4) {
        int r  = tid >> 2;
        int c0 = (tid & 3) << 3;
        float ax[8]={0,0,0,0,0,0,0,0}, ay[8]={0,0,0,0,0,0,0,0};
        float axx[8]={0,0,0,0,0,0,0,0}, ayy[8]={0,0,0,0,0,0,0,0};
        float axy[8]={0,0,0,0,0,0,0,0};
#pragma unroll
        for (int i = 0; i < 18; i++) {
            float x = sx[r][c0+i], y = sy[r][c0+i];
            float xx = x*x, xy = x*y;
            float yy = S0 ? 0.f : y*y;
#pragma unroll
            for (int j = 0; j < 8; j++) {
                int k = i - j;
                if (k >= 0 && k < 11) {
                    ax[j]  = fmaf(G[k], x,  ax[j]);
                    ay[j]  = fmaf(G[k], y,  ay[j]);
                    axx[j] = fmaf(G[k], xx, axx[j]);
                    if (!S0) ayy[j] = fmaf(G[k], yy, ayy[j]);
                    axy[j] = fmaf(G[k], xy, axy[j]);
                }
            }
        }
#pragma unroll
        for (int j = 0; j < 8; j++) {
            hb0[r][c0+j] = ax[j]; hb1[r][c0+j] = ay[j]; hb2[r][c0+j] = axx[j];
            if (!S0) hb3[r][c0+j] = ayy[j];
            hb4[r][c0+j] = axy[j];
        }
    }
    __syncthreads();

    // Stage 2: vertical blur + SSIM, 8-row strips.
    float lss = 0.f, lcs = 0.f;
    if (tid < 128) {
        int c  = tid & 31;
        int r0 = (tid >> 5) << 3;
        float m1[8]={0,0,0,0,0,0,0,0}, m2[8]={0,0,0,0,0,0,0,0};
        float e11[8]={0,0,0,0,0,0,0,0}, e22[8]={0,0,0,0,0,0,0,0};
        float e12[8]={0,0,0,0,0,0,0,0};
#pragma unroll
        for (int i = 0; i < 18; i++) {
            int row = r0 + i;
            float v0 = hb0[row][c], v1 = hb1[row][c];
            float v2 = hb2[row][c], v4 = hb4[row][c];
            float v3 = S0 ? 0.f : hb3[row][c];
#pragma unroll
            for (int j = 0; j < 8; j++) {
                int k = i - j;
                if (k >= 0 && k < 11) {
                    m1[j]  = fmaf(G[k], v0, m1[j]);
                    m2[j]  = fmaf(G[k], v1, m2[j]);
                    e11[j] = fmaf(G[k], v2, e11[j]);
                    if (!S0) e22[j] = fmaf(G[k], v3, e22[j]);
                    e12[j] = fmaf(G[k], v4, e12[j]);
                }
            }
        }
        int ow = tx0 + c;
#pragma unroll
        for (int j = 0; j < 8; j++) {
            int oh = ty0 + r0 + j;
            if (oh < OH && ow < OH) {
                float M1 = m1[j], M2 = m2[j];
                float E22 = S0 ? M2 : e22[j];
                float m11 = M1*M1, m22 = M2*M2, m12 = M1*M2;
                float v1 = e11[j] - m11, v2 = E22 - m22, cov = e12[j] - m12;
                float cs = __fdividef(2.f*cov + 0.0009f, v1 + v2 + 0.0009f);
                float sv = __fdividef(2.f*m12 + 0.0001f, m11 + m22 + 0.0001f) * cs;
                lss += sv; lcs += cs;
            }
        }
    }

    // Block reduction -> atomics.
#pragma unroll
    for (int o = 16; o; o >>= 1) {
        lss += __shfl_down_sync(0xffffffffu, lss, o);
        lcs += __shfl_down_sync(0xffffffffu, lcs, o);
    }
    if ((tid & 31) == 0) { rss[tid>>5] = lss; rcs[tid>>5] = lcs; }
    __syncthreads();
    if (tid == 0) {
        float ts = 0.f, tc = 0.f;
#pragma unroll
        for (int w = 0; w < NTHR/32; w++) { ts += rss[w]; tc += rcs[w]; }
        atomicAdd(&g_ss[sidx*NBC + bc], ts);
        atomicAdd(&g_cs[sidx*NBC + bc], tc);
    }
}

// ---------------------------------------------------------------------------
__global__ void finalize(float* __restrict__ out)
{
    __shared__ float sm[NBC];
    int t = threadIdx.x;
    const float Wt[5]  = {0.0448f, 0.2856f, 0.3001f, 0.2363f, 0.1333f};
    const float cnt[5] = {502.f*502.f, 246.f*246.f, 118.f*118.f, 54.f*54.f, 22.f*22.f};
    if (t < NBC) {
        float ms = 1.f;
#pragma unroll
        for (int s = 0; s < NSCALES; s++) {
            float acc = (s == NSCALES-1) ? g_ss[s*NBC + t] : g_cs[s*NBC + t];
            float v = fmaxf(acc / cnt[s], 0.f);
            ms *= powf(v, Wt[s]);
        }
        sm[t] = ms;
    }
    __syncthreads();
    if (t == 0) {
        float a = 0.f;
#pragma unroll
        for (int i = 0; i < NBC; i++) a += sm[i];
        out[0] = 1.f - a / (float)NBC;
    }
}

// ---------------------------------------------------------------------------
extern "C" void kernel_launch(void* const* d_in, const int* in_sizes, int n_in,
                              void* d_out, int out_size)
{
    const float* pred = (const float*)d_in[0];
    const int*   tgt  = (const int*)d_in[1];
    float*       out  = (float*)d_out;

    int np = BB*HH0*HH0;
    softmax_x0<<<(np + 255)/256, 256>>>(pred, tgt);

    int Hs = HH0;
    for (int s = 0; s < NSCALES; s++) {
        int OH = Hs - 10;
        int nt = (OH + TS - 1)/TS;
        dim3 grid(nt, nt, NBC);
        if (s == 0) ssim_kernel<true ><<<grid, NTHR>>>(tgt, Hs, s);
        else        ssim_kernel<false><<<grid, NTHR>>>(tgt, Hs, s);
        if (s < 4) Hs >>= 1;
    }

    finalize<<<1, 64>>>(out);
}